// round 3
// baseline (speedup 1.0000x reference)
#include <cuda_runtime.h>

// UnPooling: stride-2 zero-insertion unpool.
// in:  [B=32, H=112, W=112, C=64] fp32
// out: [B=32, 224, 224, 64] fp32; out[b, 2h, 2w, c] = in[b, h, w, c], else 0.
//
// Input-driven mapping: one thread per input float4. Each thread:
//   - loads 1 float4 (fully coalesced, all 32 lanes active, 512B/warp)
//   - stores it to the even output pixel of row 2h
//   - stores zeros to the adjacent odd pixel of row 2h
//   - stores zeros to the two corresponding positions of row 2h+1
// Branch-free, no predicated-off lanes; j0 covers even pixels and j1 odd
// pixels, so together they tile both output rows exactly.
//
// Grid (7, 112, 32): x = 256-f4 chunk of the input row, y = input row h,
// z = batch. 7*256 = 1792 = W*C4 exactly, so no bounds checks.

constexpr int H    = 112;
constexpr int W    = 112;
constexpr int C4   = 16;          // 64 floats = 16 float4 per pixel
constexpr int OH   = 224;
constexpr int ROW4 = 224 * C4;    // 3584 float4 per output row
constexpr int IROW4 = W * C4;     // 1792 float4 per input row

__global__ void __launch_bounds__(256)
unpool_zi_kernel(const float4* __restrict__ in, float4* __restrict__ out)
{
    const unsigned base = blockIdx.x * 256u + threadIdx.x;   // 0..1791
    const unsigned h    = blockIdx.y;
    const unsigned b    = blockIdx.z;

    const float4 v = __ldcs(in + (size_t)(b * H + h) * IROW4 + base);

    const unsigned c4 = base & 15u;
    const unsigned j0 = ((base >> 4) << 5) + c4;  // even output pixel slot
    const unsigned j1 = j0 + 16u;                 // adjacent odd pixel slot

    float4* oeven = out + (size_t)(b * OH + 2u * h) * ROW4;
    float4* oodd  = oeven + ROW4;

    const float4 z = make_float4(0.f, 0.f, 0.f, 0.f);

    __stcs(oeven + j0, v);
    __stcs(oeven + j1, z);
    __stcs(oodd  + j0, z);
    __stcs(oodd  + j1, z);
}

extern "C" void kernel_launch(void* const* d_in, const int* in_sizes, int n_in,
                              void* d_out, int out_size)
{
    const float4* in  = (const float4*)d_in[0];
    float4*       out = (float4*)d_out;

    dim3 grid(IROW4 / 256, H, 32);   // (7, 112, 32)
    unpool_zi_kernel<<<grid, 256>>>(in, out);
}

// round 4
// speedup vs baseline: 1.0753x; 1.0753x over previous
#include <cuda_runtime.h>

// UnPooling: stride-2 zero-insertion unpool.
// in:  [B=32, H=112, W=112, C=64] fp32
// out: [B=32, 224, 224, 64] fp32; out[b, 2h, 2w, c] = in[b, h, w, c], else 0.
//
// Output-driven mapping (R2 structure — store stream fully linear per warp):
// grid (7, 224, 32): x = 512-float4 chunk of the output row, y = output row,
// z = batch. Odd rows: pure zero fill. Even rows: 2 float4 per thread.
//
// R3 lesson: input-driven scatter doubles L1tex store wavefronts (interleaved
// segments) — keep the 411MB store stream contiguous, predicate the loads.
//
// R4 change: DEFAULT stores (no .cs) on the output so dirty lines persist in
// the 126MB L2; under graph-replay steady state, lines rewritten before
// drain never touch DRAM (measured R2 traffic 457MB < 514MB naive floor —
// amplify that effect). Loads keep .cs (single-use read stream).

constexpr int B    = 32;
constexpr int H    = 112;
constexpr int C4   = 16;          // 64 floats = 16 float4 per pixel
constexpr int OH   = 224;
constexpr int ROW4 = 224 * C4;    // 3584 float4 per output row
constexpr int IROW4 = 112 * C4;   // 1792 float4 per input row
constexpr int CHUNK = 512;        // float4 per block (2 per thread)

__global__ void __launch_bounds__(256)
unpool_zi_kernel(const float4* __restrict__ in, float4* __restrict__ out)
{
    const unsigned tid  = threadIdx.x;
    const unsigned oh   = blockIdx.y;
    const unsigned b    = blockIdx.z;
    const unsigned base = blockIdx.x * (unsigned)CHUNK + tid;

    float4* orow = out + (size_t)(b * OH + oh) * ROW4;

    const float4 z = make_float4(0.f, 0.f, 0.f, 0.f);

    if (oh & 1u) {
        // Entire row is zero: pure streaming store, no loads.
        orow[base]        = z;
        orow[base + 256u] = z;
        return;
    }

    const float4* irow = in + (size_t)(b * H + (oh >> 1)) * IROW4;

    const unsigned j0 = base;
    const unsigned j1 = base + 256u;

    const unsigned ow0 = j0 >> 4, c40 = j0 & 15u;
    const unsigned ow1 = j1 >> 4, c41 = j1 & 15u;

    float4 v0 = z, v1 = z;
    if (!(ow0 & 1u)) v0 = __ldcs(irow + (ow0 >> 1) * C4 + c40);
    if (!(ow1 & 1u)) v1 = __ldcs(irow + (ow1 >> 1) * C4 + c41);

    orow[j0] = v0;
    orow[j1] = v1;
}

extern "C" void kernel_launch(void* const* d_in, const int* in_sizes, int n_in,
                              void* d_out, int out_size)
{
    const float4* in  = (const float4*)d_in[0];
    float4*       out = (float4*)d_out;

    dim3 grid(ROW4 / CHUNK, OH, B);   // (7, 224, 32)
    unpool_zi_kernel<<<grid, 256>>>(in, out);
}